// round 9
// baseline (speedup 1.0000x reference)
#include <cuda_runtime.h>

#define BSZ  512
#define NN   128
#define NMAT 2560
#define SS   132             // padded row stride (words): 132 ≡ 4 (mod 32)
#define NCTA 296             // persistent grid: CTAs 0..191 do 9, rest 8

__device__ __forceinline__ float frcp(float x) {
    float r;
    asm("rcp.approx.ftz.f32 %0, %1;" : "=f"(r) : "f"(x));
    return r;
}
__device__ __forceinline__ void barn(int id, int cnt) {
    asm volatile("bar.sync %0, %1;" :: "r"(id), "r"(cnt) : "memory");
}

// ---------------- persistent scratch (__device__ globals) -------------------
__device__ float g_Ts[128];
__device__ int   g_perm[128];
__device__ float g_A [129 * 128];
__device__ float g_Cc[129 * 128];
__device__ int   g_kidx[BSZ * NN];

// ---------------- kernel 1: rank thresholds ---------------------------------
__global__ void k_rank(const float* __restrict__ w1, const float* __restrict__ b1)
{
    __shared__ float tsh[128];
    int l = threadIdx.x;
    float w  = w1[l];
    float bb = b1[l];
    float tv;
    if (w != 0.0f) tv = -bb / w;
    else           tv = (bb > 0.0f) ? -3.0e38f : 3.0e38f;
    tsh[l] = tv;
    __syncthreads();
    int r = 0;
    for (int p = 0; p < 128; ++p) {
        float o = tsh[p];
        r += (o < tv) || (o == tv && p < l);
    }
    g_Ts[r]   = tv;
    g_perm[r] = l;
}

// ---------------- kernel 2: interval tables ---------------------------------
__global__ void k_tables(const float* __restrict__ w1, const float* __restrict__ b1,
                         const float* __restrict__ w2, const float* __restrict__ b2)
{
    __shared__ float ws[128], bs[128];
    __shared__ int   ps[128];
    int k = blockIdx.x;       // 0..128
    int j = threadIdx.x;      // 0..127
    ps[j] = g_perm[j];
    __syncthreads();
    ws[j] = w1[ps[j]];
    bs[j] = b1[ps[j]];
    __syncthreads();
    float a = 0.f, c = 0.f;
    #pragma unroll 4
    for (int p = 0; p < 128; ++p) {
        float w  = ws[p];
        float bb = bs[p];
        bool pos = (w > 0.f) || (w == 0.f && bb > 0.f);
        bool act = pos ? (p < k) : (p >= k);
        if (act) {
            float wv = w2[j * 128 + ps[p]];
            a = fmaf(w,  wv, a);
            c = fmaf(bb, wv, c);
        }
    }
    g_A [k * 128 + j] = a;
    g_Cc[k * 128 + j] = c + b2[j];
}

// ---------------- kernel 3: interval index per scalar -----------------------
__global__ void k_kidx(const float* __restrict__ x)
{
    int i = blockIdx.x * blockDim.x + threadIdx.x;
    if (i >= BSZ * NN) return;
    float xv = x[i];
    int lo = 0, hi = 128;
    while (lo < hi) {
        int mid = (lo + hi) >> 1;
        if (g_Ts[mid] < xv) lo = mid + 1; else hi = mid;
    }
    g_kidx[i] = lo;
}

// ---------------- kernel 4: persistent, prefetch-pipelined Sinkhorn ---------
// Each CTA processes 8-9 matrices. Two padded 128x132 buffers ping-pong:
// while the register-resident loop runs on matrix m, cp.async streams matrix
// m+1's noise into the other buffer (padded layout written directly).
__global__ __launch_bounds__(512, 1) void k_sinkhorn(
    const float* __restrict__ x,
    const float* __restrict__ noise,
    float* __restrict__ out)
{
    extern __shared__ float sm[];
    float* S0  = sm;                      // [128][SS]
    float* S1  = S0 + 128 * SS;           // [128][SS]
    float* P1  = S1 + 128 * SS;           // [2][128*5]
    float* P2  = P1 + 2 * 128 * 5;        // [2][4][SS]
    float* CvW = P2 + 2 * 4 * SS;         // [16][32]
    float* xs  = CvW + 16 * 32;           // [128]
    int*   ks  = (int*)(xs + 128);        // [128]

    const int tid  = threadIdx.x;
    const int lane = tid & 31;
    const int wrp  = tid >> 5;
    const int g    = wrp >> 2;
    const int q    = wrp & 3;
    const int r    = 32 * g + lane;
    const int msw  = (lane >> 1) & 12;

    const int k    = blockIdx.x;
    const int cnt   = (k < 192) ? 9 : 8;
    const int mbase = (k < 192) ? k * 9 : 1728 + (k - 192) * 8;

    const unsigned int s0u = (unsigned int)__cvta_generic_to_shared(S0);
    const unsigned int s1u = (unsigned int)__cvta_generic_to_shared(S1);

    // per-thread copy geometry (shared by prefetch / prologue / store-out)
    int rowh[8], c4h[8];
    #pragma unroll
    for (int h = 0; h < 8; ++h) {
        int id = h * 512 + tid;
        rowh[h] = id >> 5;                // row, uniform per warp
        c4h[h]  = (id & 31) * 4;          // 4*lane
    }

    // ---- prefetch matrix mbase into S0 -------------------------------------
    {
        const float* src = noise + (size_t)mbase * (NN * NN);
        #pragma unroll
        for (int h = 0; h < 8; ++h) {
            unsigned int dst = s0u + (unsigned int)(rowh[h] * SS + c4h[h]) * 4u;
            asm volatile("cp.async.cg.shared.global [%0], [%1], 16;"
                         :: "r"(dst), "l"(src + (size_t)(h * 512 + tid) * 4)
                         : "memory");
        }
        asm volatile("cp.async.commit_group;" ::: "memory");
    }

    for (int i = 0; i < cnt; ++i) {
        const int m = mbase + i;
        const int b = m & (BSZ - 1);
        float* cur = (i & 1) ? S1 : S0;
        const unsigned int nxtu = (i & 1) ? s0u : s1u;

        if (tid < 128) {
            xs[tid] = x[b * NN + tid];
            ks[tid] = g_kidx[b * NN + tid];
        }
        asm volatile("cp.async.wait_group 0;" ::: "memory");
        __syncthreads();

        // ---- prologue: in-place exp on cur (noise -> M0) -------------------
        #pragma unroll
        for (int h = 0; h < 8; ++h) {
            int row = rowh[h], c4 = c4h[h];
            int   kr = ks[row];
            float xv = xs[row];
            float4 a4 = *(const float4*)(g_A  + kr * 128 + c4);
            float4 q4 = *(const float4*)(g_Cc + kr * 128 + c4);
            float4 n4 = *(const float4*)(cur + row * SS + c4);
            float4 e;
            e.x = __expf(fmaf(a4.x, xv, q4.x) + n4.x);
            e.y = __expf(fmaf(a4.y, xv, q4.y) + n4.y);
            e.z = __expf(fmaf(a4.z, xv, q4.z) + n4.z);
            e.w = __expf(fmaf(a4.w, xv, q4.w) + n4.w);
            *(float4*)(cur + row * SS + c4) = e;
        }
        __syncthreads();

        // ---- pickup permuted row slice into registers ----------------------
        float4 rr[8];
        float* af = (float*)rr;
        #pragma unroll
        for (int t = 0; t < 8; ++t)
            rr[t] = *(const float4*)(cur + r * SS + 32 * q + ((4 * t) ^ msw));

        // ---- prefetch next matrix into the other buffer (overlaps loop) ----
        if (i + 1 < cnt) {
            const float* src = noise + (size_t)(m + 1) * (NN * NN);
            #pragma unroll
            for (int h = 0; h < 8; ++h) {
                unsigned int dst = nxtu + (unsigned int)(rowh[h] * SS + c4h[h]) * 4u;
                asm volatile("cp.async.cg.shared.global [%0], [%1], 16;"
                             :: "r"(dst), "l"(src + (size_t)(h * 512 + tid) * 4)
                             : "memory");
            }
            asm volatile("cp.async.commit_group;" ::: "memory");
        }

        // ---- 10 evolving-Sinkhorn iterations -------------------------------
        #pragma unroll 2
        for (int it = 0; it < 10; ++it) {
            float* P1b = P1 + (it & 1) * (128 * 5);
            float* P2b = P2 + (it & 1) * (4 * SS);

            // (1) row sum -> group-local partial
            float4 t0 = make_float4(rr[0].x + rr[4].x, rr[0].y + rr[4].y,
                                    rr[0].z + rr[4].z, rr[0].w + rr[4].w);
            float4 t1 = make_float4(rr[1].x + rr[5].x, rr[1].y + rr[5].y,
                                    rr[1].z + rr[5].z, rr[1].w + rr[5].w);
            float4 t2 = make_float4(rr[2].x + rr[6].x, rr[2].y + rr[6].y,
                                    rr[2].z + rr[6].z, rr[2].w + rr[6].w);
            float4 t3 = make_float4(rr[3].x + rr[7].x, rr[3].y + rr[7].y,
                                    rr[3].z + rr[7].z, rr[3].w + rr[7].w);
            t0.x += t2.x; t0.y += t2.y; t0.z += t2.z; t0.w += t2.w;
            t1.x += t3.x; t1.y += t3.y; t1.z += t3.z; t1.w += t3.w;
            t0.x += t1.x; t0.y += t1.y; t0.z += t1.z; t0.w += t1.w;
            P1b[r * 5 + q] = (t0.x + t0.y) + (t0.z + t0.w);
            barn(1 + g, 128);

            // (2) re-derive R; scale rows in place
            float rs = (P1b[r * 5 + 0] + P1b[r * 5 + 1]) +
                       (P1b[r * 5 + 2] + P1b[r * 5 + 3]);
            float R_own = frcp(rs);
            #pragma unroll
            for (int kk = 0; kk < 8; ++kk) {
                rr[kk].x *= R_own; rr[kk].y *= R_own;
                rr[kk].z *= R_own; rr[kk].w *= R_own;
            }

            // (3) column sums: two select-light butterfly passes
            #pragma unroll
            for (int pass = 0; pass < 2; ++pass) {
                const int cb = 16 * pass;
                float w8[8];
                #pragma unroll
                for (int j = 0; j < 8; ++j)
                    w8[j] = af[cb + j] +
                            __shfl_xor_sync(0xffffffffu, af[cb + j + 8], 16);
                float w4[4];
                #pragma unroll
                for (int j = 0; j < 4; ++j)
                    w4[j] = w8[j] + __shfl_xor_sync(0xffffffffu, w8[j + 4], 8);
                float w2v[2];
                bool u4 = (lane & 4) != 0;
                #pragma unroll
                for (int j = 0; j < 2; ++j) {
                    float sd = u4 ? w4[j] : w4[j + 2];
                    float kp = u4 ? w4[j + 2] : w4[j];
                    w2v[j] = kp + __shfl_xor_sync(0xffffffffu, sd, 4);
                }
                bool u2b = (lane & 2) != 0;
                float sd = u2b ? w2v[0] : w2v[1];
                float kp = u2b ? w2v[1] : w2v[0];
                float w1 = kp + __shfl_xor_sync(0xffffffffu, sd, 2);
                float v  = w1 + __shfl_xor_sync(0xffffffffu, w1, 1);
                if (!(lane & 1))
                    P2b[g * SS + 32 * q + cb + ((lane >> 1) & 15)] = v;
            }
            barn(5 + q, 128);

            // (4) per-warp C for own quarter
            {
                int cidx = 32 * q + lane;
                float cs = (P2b[cidx] + P2b[SS + cidx]) +
                           (P2b[2 * SS + cidx] + P2b[3 * SS + cidx]);
                CvW[wrp * 32 + lane] = frcp(cs);
            }
            __syncwarp();

            // (5) scale columns in place
            #pragma unroll
            for (int t = 0; t < 8; ++t) {
                float4 c4 = *(const float4*)(CvW + wrp * 32 + ((4 * t) ^ msw));
                rr[t].x *= c4.x; rr[t].y *= c4.y;
                rr[t].z *= c4.z; rr[t].w *= c4.w;
            }
        }

        // ---- epilogue: transpose via cur, streaming store ------------------
        #pragma unroll
        for (int t = 0; t < 8; ++t) {
            int col = 32 * q + ((4 * t) ^ msw);
            cur[(col + 0) * SS + r] = rr[t].x;
            cur[(col + 1) * SS + r] = rr[t].y;
            cur[(col + 2) * SS + r] = rr[t].z;
            cur[(col + 3) * SS + r] = rr[t].w;
        }
        __syncthreads();
        float* om = out + (size_t)m * (NN * NN);
        #pragma unroll
        for (int h = 0; h < 8; ++h) {
            float4 v = *(const float4*)(cur + rowh[h] * SS + c4h[h]);
            __stcs((float4*)(om + (size_t)(h * 512 + tid) * 4), v);
        }
        __syncthreads();   // all LDS of cur done before it becomes a prefetch dst
    }
}

// ---------------- launch ----------------------------------------------------
extern "C" void kernel_launch(void* const* d_in, const int* in_sizes, int n_in,
                              void* d_out, int out_size)
{
    const float* x     = (const float*)d_in[0];
    const float* w1    = (const float*)d_in[1];
    const float* b1    = (const float*)d_in[2];
    const float* w2    = (const float*)d_in[3];
    const float* b2    = (const float*)d_in[4];
    const float* noise = (const float*)d_in[5];
    float* out = (float*)d_out;

    k_rank  <<<1,   128>>>(w1, b1);
    k_tables<<<129, 128>>>(w1, b1, w2, b2);
    k_kidx  <<<256, 256>>>(x);

    // S0 + S1 + P1(x2) + P2(x2) + CvW + xs + ks
    const int smem_words = 2 * 128 * SS + 2 * 128 * 5 + 2 * 4 * SS
                         + 16 * 32 + 128 + 128;
    const int smem_bytes = smem_words * 4;               // 147,584 B
    cudaFuncSetAttribute(k_sinkhorn, cudaFuncAttributeMaxDynamicSharedMemorySize,
                         smem_bytes);
    k_sinkhorn<<<NCTA, 512, smem_bytes>>>(x, noise, out);
}

// round 10
// speedup vs baseline: 1.0854x; 1.0854x over previous
#include <cuda_runtime.h>

#define BSZ  512
#define NN   128
#define NMAT 2560
#define SS   132             // stage row stride (words): 132 ≡ 4 (mod 32)

__device__ __forceinline__ float frcp(float x) {
    float r;
    asm("rcp.approx.ftz.f32 %0, %1;" : "=f"(r) : "f"(x));
    return r;
}
__device__ __forceinline__ void barn(int id, int cnt) {
    asm volatile("bar.sync %0, %1;" :: "r"(id), "r"(cnt) : "memory");
}

// ---------------- persistent scratch (__device__ globals) -------------------
__device__ float g_Ts[128];
__device__ int   g_perm[128];
__device__ float g_A [129 * 128];
__device__ float g_Cc[129 * 128];
__device__ int   g_kidx[BSZ * NN];

// ---------------- kernel 1: rank thresholds ---------------------------------
__global__ void k_rank(const float* __restrict__ w1, const float* __restrict__ b1)
{
    __shared__ float tsh[128];
    int l = threadIdx.x;
    float w  = w1[l];
    float bb = b1[l];
    float tv;
    if (w != 0.0f) tv = -bb / w;
    else           tv = (bb > 0.0f) ? -3.0e38f : 3.0e38f;
    tsh[l] = tv;
    __syncthreads();
    int r = 0;
    for (int p = 0; p < 128; ++p) {
        float o = tsh[p];
        r += (o < tv) || (o == tv && p < l);
    }
    g_Ts[r]   = tv;
    g_perm[r] = l;
}

// ---------------- kernel 2: interval tables ---------------------------------
__global__ void k_tables(const float* __restrict__ w1, const float* __restrict__ b1,
                         const float* __restrict__ w2, const float* __restrict__ b2)
{
    __shared__ float ws[128], bs[128];
    __shared__ int   ps[128];
    int k = blockIdx.x;       // 0..128
    int j = threadIdx.x;      // 0..127
    ps[j] = g_perm[j];
    __syncthreads();
    ws[j] = w1[ps[j]];
    bs[j] = b1[ps[j]];
    __syncthreads();
    float a = 0.f, c = 0.f;
    #pragma unroll 4
    for (int p = 0; p < 128; ++p) {
        float w  = ws[p];
        float bb = bs[p];
        bool pos = (w > 0.f) || (w == 0.f && bb > 0.f);
        bool act = pos ? (p < k) : (p >= k);
        if (act) {
            float wv = w2[j * 128 + ps[p]];
            a = fmaf(w,  wv, a);
            c = fmaf(bb, wv, c);
        }
    }
    g_A [k * 128 + j] = a;
    g_Cc[k * 128 + j] = c + b2[j];
}

// ---------------- kernel 3: interval index per scalar -----------------------
__global__ void k_kidx(const float* __restrict__ x)
{
    int i = blockIdx.x * blockDim.x + threadIdx.x;
    if (i >= BSZ * NN) return;
    float xv = x[i];
    int lo = 0, hi = 128;
    while (lo < hi) {
        int mid = (lo + hi) >> 1;
        if (g_Ts[mid] < xv) lo = mid + 1; else hi = mid;
    }
    g_kidx[i] = lo;
}

// ---------------- kernel 4: register-resident evolving Sinkhorn -------------
// warp w: g=w>>2 (row group), q=w&3 (column quarter); lane -> row r=32g+lane.
// Slice columns are PERMUTED: af[cb+j] = M[r][32q + cb + (j^msw)],
// msw=(lane>>1)&12, so butterfly stages off=16/off=8 are select-free.
// Sync: 2 named barriers per iteration (128 threads each), partials
// double-buffered on iteration parity.
// NEW vs R7: prefetch.global.L2 of noise[m+296] (next CTA on this SM) issued
// after pickup, and streaming (__stcs) epilogue stores.
__global__ __launch_bounds__(512, 2) void k_sinkhorn(
    const float* __restrict__ x,
    const float* __restrict__ noise,
    float* __restrict__ out)
{
    extern __shared__ float sm[];
    float* stage = sm;                    // [128][SS]
    float* P1    = sm + 128 * SS;         // [2][128*5]
    float* P2    = P1 + 2 * 128 * 5;      // [2][4][SS]
    float* CvW   = P2 + 2 * 4 * SS;       // [16][32] per-warp C copies
    float* xs    = CvW + 16 * 32;         // [128]
    int*   ks    = (int*)(xs + 128);      // [128]

    const int m    = blockIdx.x;
    const int b    = m & (BSZ - 1);
    const int tid  = threadIdx.x;
    const int lane = tid & 31;
    const int wrp  = tid >> 5;
    const int g    = wrp >> 2;
    const int q    = wrp & 3;
    const int r    = 32 * g + lane;
    const int msw  = (lane >> 1) & 12;

    if (tid < 128) {
        xs[tid] = x[b * NN + tid];
        ks[tid] = g_kidx[b * NN + tid];
    }
    __syncthreads();

    // ---- prologue: build M0 into stage[row][col], fully coalesced ----------
    const float* nzm = noise + (size_t)m * (NN * NN);
    #pragma unroll
    for (int h = 0; h < 8; ++h) {
        int id  = h * 512 + tid;          // float4 index; row uniform per warp
        int row = id >> 5;
        int c4  = (id & 31) * 4;
        int   kr = ks[row];
        float xv = xs[row];
        float4 a4 = *(const float4*)(g_A  + kr * 128 + c4);
        float4 q4 = *(const float4*)(g_Cc + kr * 128 + c4);
        float4 n4 = *(const float4*)(nzm + id * 4);
        float4 e;
        e.x = __expf(fmaf(a4.x, xv, q4.x) + n4.x);
        e.y = __expf(fmaf(a4.y, xv, q4.y) + n4.y);
        e.z = __expf(fmaf(a4.z, xv, q4.z) + n4.z);
        e.w = __expf(fmaf(a4.w, xv, q4.w) + n4.w);
        *(float4*)(stage + row * SS + c4) = e;
    }
    __syncthreads();

    // ---- pick up permuted row slice into registers -------------------------
    float4 rr[8];
    float* af = (float*)rr;
    #pragma unroll
    for (int t = 0; t < 8; ++t)
        rr[t] = *(const float4*)(stage + r * SS + 32 * q + ((4 * t) ^ msw));

    // ---- L2-prefetch the noise of the CTA that will follow on this SM ------
    if (m + 296 < NMAT) {
        const char* pf = (const char*)(noise + (size_t)(m + 296) * (NN * NN));
        asm volatile("prefetch.global.L2 [%0];" :: "l"(pf + tid * 128) : "memory");
    }

    // ---- 10 evolving-Sinkhorn iterations -----------------------------------
    #pragma unroll 2
    for (int it = 0; it < 10; ++it) {
        float* P1b = P1 + (it & 1) * (128 * 5);
        float* P2b = P2 + (it & 1) * (4 * SS);

        // (1) row sum (float4 tree) -> group-local partial
        float4 t0 = make_float4(rr[0].x + rr[4].x, rr[0].y + rr[4].y,
                                rr[0].z + rr[4].z, rr[0].w + rr[4].w);
        float4 t1 = make_float4(rr[1].x + rr[5].x, rr[1].y + rr[5].y,
                                rr[1].z + rr[5].z, rr[1].w + rr[5].w);
        float4 t2 = make_float4(rr[2].x + rr[6].x, rr[2].y + rr[6].y,
                                rr[2].z + rr[6].z, rr[2].w + rr[6].w);
        float4 t3 = make_float4(rr[3].x + rr[7].x, rr[3].y + rr[7].y,
                                rr[3].z + rr[7].z, rr[3].w + rr[7].w);
        t0.x += t2.x; t0.y += t2.y; t0.z += t2.z; t0.w += t2.w;
        t1.x += t3.x; t1.y += t3.y; t1.z += t3.z; t1.w += t3.w;
        t0.x += t1.x; t0.y += t1.y; t0.z += t1.z; t0.w += t1.w;
        P1b[r * 5 + q] = (t0.x + t0.y) + (t0.z + t0.w);
        barn(1 + g, 128);

        // (2) re-derive R per thread; scale rows in place
        float rs = (P1b[r * 5 + 0] + P1b[r * 5 + 1]) +
                   (P1b[r * 5 + 2] + P1b[r * 5 + 3]);
        float R_own = frcp(rs);
        #pragma unroll
        for (int k = 0; k < 8; ++k) {
            rr[k].x *= R_own; rr[k].y *= R_own;
            rr[k].z *= R_own; rr[k].w *= R_own;
        }

        // (3) column sums: two select-light butterfly passes over warp rows
        #pragma unroll
        for (int pass = 0; pass < 2; ++pass) {
            const int cb = 16 * pass;
            float w8[8];
            #pragma unroll
            for (int j = 0; j < 8; ++j)     // col bit3 <- lane bit4 (pre-swizzled)
                w8[j] = af[cb + j] +
                        __shfl_xor_sync(0xffffffffu, af[cb + j + 8], 16);
            float w4[4];
            #pragma unroll
            for (int j = 0; j < 4; ++j)     // col bit2 <- lane bit3 (pre-swizzled)
                w4[j] = w8[j] + __shfl_xor_sync(0xffffffffu, w8[j + 4], 8);
            float w2v[2];
            bool u4 = (lane & 4) != 0;      // col bit1 <- lane bit2 (select)
            #pragma unroll
            for (int j = 0; j < 2; ++j) {
                float sd = u4 ? w4[j] : w4[j + 2];
                float kp = u4 ? w4[j + 2] : w4[j];
                w2v[j] = kp + __shfl_xor_sync(0xffffffffu, sd, 4);
            }
            bool u2b = (lane & 2) != 0;     // col bit0 <- lane bit1 (select)
            float sd = u2b ? w2v[0] : w2v[1];
            float kp = u2b ? w2v[1] : w2v[0];
            float w1 = kp + __shfl_xor_sync(0xffffffffu, sd, 2);
            float v  = w1 + __shfl_xor_sync(0xffffffffu, w1, 1);  // rows: bit0
            if (!(lane & 1))
                P2b[g * SS + 32 * q + cb + ((lane >> 1) & 15)] = v;
        }
        barn(5 + q, 128);

        // (4) per-warp C for own quarter (redundant across the 4 g-warps)
        {
            int cidx = 32 * q + lane;
            float cs = (P2b[cidx] + P2b[SS + cidx]) +
                       (P2b[2 * SS + cidx] + P2b[3 * SS + cidx]);
            CvW[wrp * 32 + lane] = frcp(cs);
        }
        __syncwarp();

        // (5) scale columns in place (swizzle-aligned vec4 broadcast)
        #pragma unroll
        for (int t = 0; t < 8; ++t) {
            float4 c4 = *(const float4*)(CvW + wrp * 32 + ((4 * t) ^ msw));
            rr[t].x *= c4.x; rr[t].y *= c4.y;
            rr[t].z *= c4.z; rr[t].w *= c4.w;
        }
    }

    // ---- epilogue: registers hold final M; transpose via stage -------------
    #pragma unroll
    for (int t = 0; t < 8; ++t) {
        int col = 32 * q + ((4 * t) ^ msw);
        stage[(col + 0) * SS + r] = rr[t].x;
        stage[(col + 1) * SS + r] = rr[t].y;
        stage[(col + 2) * SS + r] = rr[t].z;
        stage[(col + 3) * SS + r] = rr[t].w;
    }
    __syncthreads();
    float* om = out + (size_t)m * (NN * NN);
    #pragma unroll
    for (int h = 0; h < 8; ++h) {
        int id  = h * 512 + tid;
        int row = id >> 5;
        int c4  = (id & 31) * 4;
        float4 v = *(const float4*)(stage + row * SS + c4);
        __stcs((float4*)(om + (size_t)id * 4), v);   // streaming: skip L2 fill
    }
}

// ---------------- launch ----------------------------------------------------
extern "C" void kernel_launch(void* const* d_in, const int* in_sizes, int n_in,
                              void* d_out, int out_size)
{
    const float* x     = (const float*)d_in[0];
    const float* w1    = (const float*)d_in[1];
    const float* b1    = (const float*)d_in[2];
    const float* w2    = (const float*)d_in[3];
    const float* b2    = (const float*)d_in[4];
    const float* noise = (const float*)d_in[5];
    float* out = (float*)d_out;

    k_rank  <<<1,   128>>>(w1, b1);
    k_tables<<<129, 128>>>(w1, b1, w2, b2);
    k_kidx  <<<256, 256>>>(x);

    // stage + P1(x2) + P2(x2) + CvW + xs + ks
    const int smem_words = 128 * SS + 2 * 128 * 5 + 2 * 4 * SS
                         + 16 * 32 + 128 + 128;
    const int smem_bytes = smem_words * 4;               // 80,000 B
    cudaFuncSetAttribute(k_sinkhorn, cudaFuncAttributeMaxDynamicSharedMemorySize,
                         smem_bytes);
    k_sinkhorn<<<NMAT, 512, smem_bytes>>>(x, noise, out);
}

// round 11
// speedup vs baseline: 1.0949x; 1.0088x over previous
#include <cuda_runtime.h>

#define BSZ    512
#define NN     128
#define NMAT   2560
#define SS     132           // stage row stride (words): 132 ≡ 4 (mod 32)

// ---------------- persistent scratch (__device__ globals) -------------------
__device__ float g_Ts[128];          // sorted ReLU thresholds
__device__ float g_A [129 * 128];    // per-interval slope table
__device__ float g_Cc[129 * 128];    // per-interval offset table (incl b2)

// ---------------- kernel 1: fused prep (rank + tables + Ts) -----------------
// 129 blocks x 128 threads. Every block redundantly computes the threshold
// rank sort in smem (~500 cyc, cheaper than a dependent launch), stages w2
// TRANSPOSED in smem (coalesced LDG, conflict-free STS), then block k builds
// table row k. Block 0 additionally publishes the sorted thresholds.
__global__ void k_prep(const float* __restrict__ w1, const float* __restrict__ b1,
                       const float* __restrict__ w2, const float* __restrict__ b2)
{
    __shared__ float tsh[128], wss[128], bss[128];
    __shared__ int   ps[128];
    extern __shared__ float w2t[];    // [128][129] transposed w2

    const int j = threadIdx.x;        // output column 0..127
    const int k = blockIdx.x;         // interval 0..128

    // thresholds + O(n^2) rank (strict total order -> permutation)
    float w  = w1[j];
    float bb = b1[j];
    float tv = (w != 0.0f) ? (-bb / w) : (bb > 0.0f ? -3.0e38f : 3.0e38f);
    tsh[j] = tv;
    __syncthreads();
    int r = 0;
    #pragma unroll 8
    for (int p = 0; p < 128; ++p) {
        float o = tsh[p];
        r += (o < tv) || (o == tv && p < j);
    }
    wss[r] = w;
    bss[r] = bb;
    ps[r]  = j;
    if (k == 0) g_Ts[r] = tv;

    // stage w2 transposed: iteration t reads w2 row t (coalesced),
    // writes w2t[j*129 + t] (banks (j + c) % 32, conflict-free)
    #pragma unroll 4
    for (int t = 0; t < 128; ++t)
        w2t[j * 129 + t] = w2[t * 128 + j];
    __syncthreads();

    // active set for interval k: {pos-slope, rank<k} U {neg-slope, rank>=k}
    float a = 0.f, c = 0.f;
    #pragma unroll 4
    for (int p = 0; p < 128; ++p) {
        float wv = wss[p], bv = bss[p];
        bool pos = (wv > 0.f) || (wv == 0.f && bv > 0.f);
        bool act = pos ? (p < k) : (p >= k);
        if (act) {
            float m = w2t[ps[p] * 129 + j];   // consecutive j: conflict-free
            a = fmaf(wv, m, a);
            c = fmaf(bv, m, c);
        }
    }
    g_A [k * 128 + j] = a;
    g_Cc[k * 128 + j] = c + b2[j];
}

// ---------------- kernel 2: register-resident Sinkhorn (R5 structure) -------
// warp w: g=w>>2 (row group), q=w&3 (column quarter, uniform per warp)
// lane i: row r=32g+i; thread holds M0[r][32q..32q+31] in rr[8] (float4)
__global__ __launch_bounds__(512, 2) void k_sinkhorn(
    const float* __restrict__ x,
    const float* __restrict__ noise,
    float* __restrict__ out)
{
    extern __shared__ float sm[];
    float* stage = sm;                    // [128][SS]  (prologue M0, epilogue out^T)
    float* P     = sm + 128 * SS;         // [4][SS]    cross-warp partials
    float* Rv    = P  + 4 * SS;           // [128]
    float* Cv    = Rv + 128;              // [128]
    float* xs    = Cv + 128;              // [128]
    float* Ts    = xs + 128;              // [128] sorted thresholds
    int*   ks    = (int*)(Ts + 128);      // [128] interval index per row

    const int m    = blockIdx.x;
    const int b    = m & (BSZ - 1);
    const int tid  = threadIdx.x;
    const int lane = tid & 31;
    const int wrp  = tid >> 5;
    const int g    = wrp >> 2;
    const int q    = wrp & 3;
    const int r    = 32 * g + lane;

    if (tid < 128) {
        xs[tid] = x[b * NN + tid];
        Ts[tid] = g_Ts[tid];
        Cv[tid] = 1.0f;
    }
    __syncthreads();
    if (tid < 128) {
        // interval index: count of thresholds < x  (7-step binary search)
        float xv = xs[tid];
        int lo = 0, hi = 128;
        #pragma unroll
        for (int s = 0; s < 7; ++s) {
            int mid = (lo + hi) >> 1;
            if (Ts[mid] < xv) lo = mid + 1; else hi = mid;
        }
        ks[tid] = lo;
    }
    __syncthreads();

    // ---- prologue: build M0 into stage[row][col], fully coalesced ----------
    const float* nzm = noise + (size_t)m * (NN * NN);
    #pragma unroll
    for (int h = 0; h < 8; ++h) {
        int id  = h * 512 + tid;          // float4 index; row uniform per warp
        int row = id >> 5;
        int c4  = (id & 31) * 4;
        int   kr = ks[row];               // warp-uniform broadcast
        float xv = xs[row];
        float4 a4 = *(const float4*)(g_A  + kr * 128 + c4);   // coalesced, L2-hot
        float4 q4 = *(const float4*)(g_Cc + kr * 128 + c4);
        float4 n4 = *(const float4*)(nzm + id * 4);           // coalesced
        float4 e;
        e.x = __expf(fmaf(a4.x, xv, q4.x) + n4.x);
        e.y = __expf(fmaf(a4.y, xv, q4.y) + n4.y);
        e.z = __expf(fmaf(a4.z, xv, q4.z) + n4.z);
        e.w = __expf(fmaf(a4.w, xv, q4.w) + n4.w);
        *(float4*)(stage + row * SS + c4) = e;                // conflict-free
    }
    __syncthreads();

    // ---- pick up own row quarter into registers ----------------------------
    float4 rr[8];
    #pragma unroll
    for (int p = 0; p < 8; ++p)
        rr[p] = *(const float4*)(stage + r * SS + 32 * q + 4 * p);  // CF
    const float* af = (const float*)rr;

    // ---- Sinkhorn iterations ----------------------------------------------
    float R_own = 0.f;
    for (int it = 0; it < 10; ++it) {
        // row GEMV: dot(own slice, C) — C read as all-lane broadcast
        float4 acc = make_float4(0.f, 0.f, 0.f, 0.f);
        #pragma unroll
        for (int p = 0; p < 8; ++p) {
            float4 c4 = *(const float4*)(Cv + 32 * q + 4 * p);  // same addr all lanes
            acc.x = fmaf(rr[p].x, c4.x, acc.x);
            acc.y = fmaf(rr[p].y, c4.y, acc.y);
            acc.z = fmaf(rr[p].z, c4.z, acc.z);
            acc.w = fmaf(rr[p].w, c4.w, acc.w);
        }
        P[q * SS + r] = (acc.x + acc.y) + (acc.z + acc.w);      // CF scalar STS
        __syncthreads();
        if (tid < 128) {
            float t = P[tid] + P[SS + tid] + P[2 * SS + tid] + P[3 * SS + tid];
            Rv[tid] = __fdividef(1.0f, t);
        }
        __syncthreads();
        R_own = Rv[r];

        // col GEMV: value-splitting butterfly over the warp's 32 rows,
        // two 16-column passes; R folded into stage 1.
        #pragma unroll
        for (int pass = 0; pass < 2; ++pass) {
            const int cb = 16 * pass;
            float w8[8];
            {   // stage off=16 (col bit3 <- lane bit4), x R folded in
                bool up = (lane & 16) != 0;
                #pragma unroll
                for (int j = 0; j < 8; ++j) {
                    float a_lo = af[cb + j];
                    float a_hi = af[cb + j + 8];
                    float send = (up ? a_lo : a_hi) * R_own;
                    float keep = (up ? a_hi : a_lo);
                    float recv = __shfl_xor_sync(0xffffffffu, send, 16);
                    w8[j] = fmaf(keep, R_own, recv);
                }
            }
            #pragma unroll
            for (int off = 8; off >= 2; off >>= 1) {   // col bit2..0 <- lane bit3..1
                int n = off >> 1;
                bool up = (lane & off) != 0;
                #pragma unroll
                for (int j = 0; j < n; ++j) {
                    float send = up ? w8[j] : w8[j + n];
                    float keep = up ? w8[j + n] : w8[j];
                    float recv = __shfl_xor_sync(0xffffffffu, send, off);
                    w8[j] = keep + recv;
                }
            }
            float v = w8[0] + __shfl_xor_sync(0xffffffffu, w8[0], 1);
            if ((lane & 1) == 0) {
                int c = cb + ((lane >> 1) & 15);
                P[g * SS + 32 * q + c] = v;             // 16 distinct banks: CF
            }
        }
        __syncthreads();
        if (tid < 128) {
            float t = P[tid] + P[SS + tid] + P[2 * SS + tid] + P[3 * SS + tid];
            Cv[tid] = __fdividef(1.0f, t);
        }
        __syncthreads();
    }

    // ---- epilogue: out[m][c][r] = M0[r][c]*R_r*C_c  (transpose via stage) --
    #pragma unroll
    for (int p = 0; p < 8; ++p) {
        float4 c4 = *(const float4*)(Cv + 32 * q + 4 * p);  // broadcast
        int cbase = 32 * q + 4 * p;
        float sx = rr[p].x * R_own, sy = rr[p].y * R_own;
        float sz = rr[p].z * R_own, sw = rr[p].w * R_own;
        stage[(cbase + 0) * SS + r] = sx * c4.x;            // CF scalar STS
        stage[(cbase + 1) * SS + r] = sy * c4.y;
        stage[(cbase + 2) * SS + r] = sz * c4.z;
        stage[(cbase + 3) * SS + r] = sw * c4.w;
    }
    __syncthreads();
    float* om = out + (size_t)m * (NN * NN);
    #pragma unroll
    for (int h = 0; h < 8; ++h) {
        int id  = h * 512 + tid;
        int row = id >> 5;
        int c4  = (id & 31) * 4;
        *(float4*)(om + id * 4) = *(const float4*)(stage + row * SS + c4);
    }
}

// ---------------- launch ----------------------------------------------------
extern "C" void kernel_launch(void* const* d_in, const int* in_sizes, int n_in,
                              void* d_out, int out_size)
{
    const float* x     = (const float*)d_in[0];
    const float* w1    = (const float*)d_in[1];
    const float* b1    = (const float*)d_in[2];
    const float* w2    = (const float*)d_in[3];
    const float* b2    = (const float*)d_in[4];
    const float* noise = (const float*)d_in[5];
    float* out = (float*)d_out;

    const int prep_smem = 128 * 129 * 4;                    // 66,048 B
    cudaFuncSetAttribute(k_prep, cudaFuncAttributeMaxDynamicSharedMemorySize,
                         prep_smem);
    k_prep<<<129, 128, prep_smem>>>(w1, b1, w2, b2);

    // stage + P + Rv + Cv + xs + Ts + ks
    const int smem_words = 128 * SS + 4 * SS + 6 * 128;
    const int smem_bytes = smem_words * 4;                  // 72,256 B
    cudaFuncSetAttribute(k_sinkhorn, cudaFuncAttributeMaxDynamicSharedMemorySize,
                         smem_bytes);
    k_sinkhorn<<<NMAT, 512, smem_bytes>>>(x, noise, out);
}

// round 12
// speedup vs baseline: 1.1756x; 1.0736x over previous
#include <cuda_runtime.h>

#define BSZ    512
#define NN     128
#define NMAT   2560
#define SS     132           // stage row stride (words): 132 ≡ 4 (mod 32)

__device__ __forceinline__ float frcp(float x) {
    float r;
    asm("rcp.approx.ftz.f32 %0, %1;" : "=f"(r) : "f"(x));
    return r;
}

// ---------------- persistent scratch (__device__ globals) -------------------
__device__ float g_Ts[128];          // sorted ReLU thresholds
__device__ float g_A [129 * 128];    // per-interval slope table
__device__ float g_Cc[129 * 128];    // per-interval offset table (incl b2)

// ---------------- kernel 1: fused prep (rank + tables + Ts) -----------------
__global__ void k_prep(const float* __restrict__ w1, const float* __restrict__ b1,
                       const float* __restrict__ w2, const float* __restrict__ b2)
{
    __shared__ float tsh[128], wss[128], bss[128];
    __shared__ int   ps[128];
    extern __shared__ float w2t[];    // [128][129] transposed w2

    const int j = threadIdx.x;        // output column 0..127
    const int k = blockIdx.x;         // interval 0..128

    float w  = w1[j];
    float bb = b1[j];
    float tv = (w != 0.0f) ? (-bb / w) : (bb > 0.0f ? -3.0e38f : 3.0e38f);
    tsh[j] = tv;
    __syncthreads();
    int r = 0;
    #pragma unroll 8
    for (int p = 0; p < 128; ++p) {
        float o = tsh[p];
        r += (o < tv) || (o == tv && p < j);
    }
    wss[r] = w;
    bss[r] = bb;
    ps[r]  = j;
    if (k == 0) g_Ts[r] = tv;

    #pragma unroll 4
    for (int t = 0; t < 128; ++t)
        w2t[j * 129 + t] = w2[t * 128 + j];
    __syncthreads();

    float a = 0.f, c = 0.f;
    #pragma unroll 4
    for (int p = 0; p < 128; ++p) {
        float wv = wss[p], bv = bss[p];
        bool pos = (wv > 0.f) || (wv == 0.f && bv > 0.f);
        bool act = pos ? (p < k) : (p >= k);
        if (act) {
            float mm = w2t[ps[p] * 129 + j];
            a = fmaf(wv, mm, a);
            c = fmaf(bv, mm, c);
        }
    }
    g_A [k * 128 + j] = a;
    g_Cc[k * 128 + j] = c + b2[j];
}

// ---------------- kernel 2: register-resident Sinkhorn ----------------------
// warp w: g=w>>2 (row group), q=w&3 (column quarter, uniform per warp)
// lane i: row r=32g+i; thread holds M0[r][32q..32q+31] in rr[8] (float4)
// Epilogue stores DIRECTLY from registers (coalesced column-major STG.32).
__global__ __launch_bounds__(512, 2) void k_sinkhorn(
    const float* __restrict__ x,
    const float* __restrict__ noise,
    float* __restrict__ out)
{
    extern __shared__ float sm[];
    float* stage = sm;                    // [128][SS]  (prologue M0 only)
    float* P     = sm + 128 * SS;         // [4][SS]    cross-warp partials
    float* Rv    = P  + 4 * SS;           // [128]
    float* Cv    = Rv + 128;              // [128]
    float* xs    = Cv + 128;              // [128]
    float* Ts    = xs + 128;              // [128] sorted thresholds
    int*   ks    = (int*)(Ts + 128);      // [128] interval index per row

    const int m    = blockIdx.x;
    const int b    = m & (BSZ - 1);
    const int tid  = threadIdx.x;
    const int lane = tid & 31;
    const int wrp  = tid >> 5;
    const int g    = wrp >> 2;
    const int q    = wrp & 3;
    const int r    = 32 * g + lane;

    if (tid < 128) {
        xs[tid] = x[b * NN + tid];
        Ts[tid] = g_Ts[tid];
        Cv[tid] = 1.0f;
    }
    __syncthreads();
    if (tid < 128) {
        float xv = xs[tid];
        int lo = 0, hi = 128;
        #pragma unroll
        for (int s = 0; s < 7; ++s) {
            int mid = (lo + hi) >> 1;
            if (Ts[mid] < xv) lo = mid + 1; else hi = mid;
        }
        ks[tid] = lo;
    }
    __syncthreads();

    // ---- prologue: build M0 into stage[row][col], fully coalesced ----------
    const float* nzm = noise + (size_t)m * (NN * NN);
    #pragma unroll
    for (int h = 0; h < 8; ++h) {
        int id  = h * 512 + tid;          // float4 index; row uniform per warp
        int row = id >> 5;
        int c4  = (id & 31) * 4;
        int   kr = ks[row];               // warp-uniform broadcast
        float xv = xs[row];
        float4 a4 = *(const float4*)(g_A  + kr * 128 + c4);   // coalesced
        float4 q4 = *(const float4*)(g_Cc + kr * 128 + c4);
        float4 n4 = *(const float4*)(nzm + id * 4);           // coalesced
        float4 e;
        e.x = __expf(fmaf(a4.x, xv, q4.x) + n4.x);
        e.y = __expf(fmaf(a4.y, xv, q4.y) + n4.y);
        e.z = __expf(fmaf(a4.z, xv, q4.z) + n4.z);
        e.w = __expf(fmaf(a4.w, xv, q4.w) + n4.w);
        *(float4*)(stage + row * SS + c4) = e;                // conflict-free
    }
    __syncthreads();

    // ---- pick up own row quarter into registers ----------------------------
    float4 rr[8];
    #pragma unroll
    for (int p = 0; p < 8; ++p)
        rr[p] = *(const float4*)(stage + r * SS + 32 * q + 4 * p);  // CF
    const float* af = (const float*)rr;

    // ---- Sinkhorn iterations ----------------------------------------------
    float R_own = 0.f;
    for (int it = 0; it < 10; ++it) {
        // row GEMV: dot(own slice, C) — C read as all-lane broadcast
        float4 acc = make_float4(0.f, 0.f, 0.f, 0.f);
        #pragma unroll
        for (int p = 0; p < 8; ++p) {
            float4 c4 = *(const float4*)(Cv + 32 * q + 4 * p);  // broadcast
            acc.x = fmaf(rr[p].x, c4.x, acc.x);
            acc.y = fmaf(rr[p].y, c4.y, acc.y);
            acc.z = fmaf(rr[p].z, c4.z, acc.z);
            acc.w = fmaf(rr[p].w, c4.w, acc.w);
        }
        P[q * SS + r] = (acc.x + acc.y) + (acc.z + acc.w);      // CF scalar STS
        __syncthreads();
        if (tid < 128) {
            float t = P[tid] + P[SS + tid] + P[2 * SS + tid] + P[3 * SS + tid];
            Rv[tid] = frcp(t);
        }
        __syncthreads();
        R_own = Rv[r];

        // col GEMV: value-splitting butterfly over the warp's 32 rows,
        // two 16-column passes; R folded into stage 1.
        #pragma unroll
        for (int pass = 0; pass < 2; ++pass) {
            const int cb = 16 * pass;
            float w8[8];
            {   // stage off=16 (col bit3 <- lane bit4), x R folded in
                bool up = (lane & 16) != 0;
                #pragma unroll
                for (int j = 0; j < 8; ++j) {
                    float a_lo = af[cb + j];
                    float a_hi = af[cb + j + 8];
                    float send = (up ? a_lo : a_hi) * R_own;
                    float keep = (up ? a_hi : a_lo);
                    float recv = __shfl_xor_sync(0xffffffffu, send, 16);
                    w8[j] = fmaf(keep, R_own, recv);
                }
            }
            #pragma unroll
            for (int off = 8; off >= 2; off >>= 1) {   // col bit2..0 <- lane bit3..1
                int n = off >> 1;
                bool up = (lane & off) != 0;
                #pragma unroll
                for (int j = 0; j < n; ++j) {
                    float send = up ? w8[j] : w8[j + n];
                    float keep = up ? w8[j + n] : w8[j];
                    float recv = __shfl_xor_sync(0xffffffffu, send, off);
                    w8[j] = keep + recv;
                }
            }
            float v = w8[0] + __shfl_xor_sync(0xffffffffu, w8[0], 1);
            if ((lane & 1) == 0) {
                int c = cb + ((lane >> 1) & 15);
                P[g * SS + 32 * q + c] = v;             // 16 distinct banks: CF
            }
        }
        __syncthreads();
        if (tid < 128) {
            float t = P[tid] + P[SS + tid] + P[2 * SS + tid] + P[3 * SS + tid];
            Cv[tid] = frcp(t);
        }
        __syncthreads();
    }

    // ---- epilogue: out[m][c][r] = M0[r][c]*R_r*C_c, DIRECT from registers --
    // For each of the thread's 32 columns c = 32q+p, the warp's 32 lanes hold
    // rows 32g..32g+31 -> out[m][c][32g+lane] is a coalesced 128B STG.32.
    {
        float* om = out + (size_t)m * (NN * NN) + (32 * q) * NN + 32 * g + lane;
        #pragma unroll
        for (int p = 0; p < 8; ++p) {
            float4 c4 = *(const float4*)(Cv + 32 * q + 4 * p);  // broadcast
            float sx = rr[p].x * R_own, sy = rr[p].y * R_own;
            float sz = rr[p].z * R_own, sw = rr[p].w * R_own;
            om[(4 * p + 0) * NN] = sx * c4.x;   // immediate-offset STG, coalesced
            om[(4 * p + 1) * NN] = sy * c4.y;
            om[(4 * p + 2) * NN] = sz * c4.z;
            om[(4 * p + 3) * NN] = sw * c4.w;
        }
    }
}

// ---------------- launch ----------------------------------------------------
extern "C" void kernel_launch(void* const* d_in, const int* in_sizes, int n_in,
                              void* d_out, int out_size)
{
    const float* x     = (const float*)d_in[0];
    const float* w1    = (const float*)d_in[1];
    const float* b1    = (const float*)d_in[2];
    const float* w2    = (const float*)d_in[3];
    const float* b2    = (const float*)d_in[4];
    const float* noise = (const float*)d_in[5];
    float* out = (float*)d_out;

    const int prep_smem = 128 * 129 * 4;                    // 66,048 B
    cudaFuncSetAttribute(k_prep, cudaFuncAttributeMaxDynamicSharedMemorySize,
                         prep_smem);
    k_prep<<<129, 128, prep_smem>>>(w1, b1, w2, b2);

    // stage + P + Rv + Cv + xs + Ts + ks
    const int smem_words = 128 * SS + 4 * SS + 6 * 128;
    const int smem_bytes = smem_words * 4;                  // 72,256 B
    cudaFuncSetAttribute(k_sinkhorn, cudaFuncAttributeMaxDynamicSharedMemorySize,
                         smem_bytes);
    k_sinkhorn<<<NMAT, 512, smem_bytes>>>(x, noise, out);
}

// round 13
// speedup vs baseline: 1.2019x; 1.0224x over previous
#include <cuda_runtime.h>

#define BSZ    512
#define NN     128
#define NMAT   2560
#define SS     132           // P stride (words): 132 ≡ 4 (mod 32)
#define TS     36            // warp subtile row stride: 36 ≡ 4 (mod 32)
#define LOG2E  1.4426950408889634f

__device__ __forceinline__ float frcp(float x) {
    float r;
    asm("rcp.approx.ftz.f32 %0, %1;" : "=f"(r) : "f"(x));
    return r;
}
__device__ __forceinline__ float fex2(float x) {
    float r;
    asm("ex2.approx.ftz.f32 %0, %1;" : "=f"(r) : "f"(x));
    return r;
}

// ---------------- persistent scratch (__device__ globals) -------------------
__device__ float g_Ts[128];          // sorted ReLU thresholds
__device__ float g_A [129 * 128];    // per-interval slope * log2e
__device__ float g_Cc[129 * 128];    // per-interval offset * log2e (incl b2)

// ---------------- kernel 1: fused prep (rank + tables + Ts) -----------------
__global__ void k_prep(const float* __restrict__ w1, const float* __restrict__ b1,
                       const float* __restrict__ w2, const float* __restrict__ b2)
{
    __shared__ float tsh[128], wss[128], bss[128];
    __shared__ int   ps[128];
    extern __shared__ float w2t[];    // [128][129] transposed w2

    const int j = threadIdx.x;        // output column 0..127
    const int k = blockIdx.x;         // interval 0..128

    float w  = w1[j];
    float bb = b1[j];
    float tv = (w != 0.0f) ? (-bb / w) : (bb > 0.0f ? -3.0e38f : 3.0e38f);
    tsh[j] = tv;
    __syncthreads();
    int r = 0;
    #pragma unroll 8
    for (int p = 0; p < 128; ++p) {
        float o = tsh[p];
        r += (o < tv) || (o == tv && p < j);
    }
    wss[r] = w;
    bss[r] = bb;
    ps[r]  = j;
    if (k == 0) g_Ts[r] = tv;

    #pragma unroll 4
    for (int t = 0; t < 128; ++t)
        w2t[j * 129 + t] = w2[t * 128 + j];
    __syncthreads();

    float a = 0.f, c = 0.f;
    #pragma unroll 4
    for (int p = 0; p < 128; ++p) {
        float wv = wss[p], bv = bss[p];
        bool pos = (wv > 0.f) || (wv == 0.f && bv > 0.f);
        bool act = pos ? (p < k) : (p >= k);
        if (act) {
            float mm = w2t[ps[p] * 129 + j];
            a = fmaf(wv, mm, a);
            c = fmaf(bv, mm, c);
        }
    }
    g_A [k * 128 + j] = a * LOG2E;                     // premultiplied log2e
    g_Cc[k * 128 + j] = (c + b2[j]) * LOG2E;
}

// ---------------- kernel 2: register-resident Sinkhorn ----------------------
// warp w: g=w>>2 (row group), q=w&3 (column quarter); lane -> row r=32g+lane.
// Prologue is WARP-LOCAL: coalesced subtile load -> warp-private padded
// subtile -> syncwarp -> row-slice pickup. No CTA barrier before iteration 1.
// Iteration 0 peeled (C==1: plain register sum). Direct-STG epilogue.
__global__ __launch_bounds__(512, 2) void k_sinkhorn(
    const float* __restrict__ x,
    const float* __restrict__ noise,
    float* __restrict__ out)
{
    extern __shared__ float sm[];
    float* sub = sm;                      // [16][32*TS] per-warp subtiles
    float* P   = sm + 16 * 32 * TS;       // [4][SS] cross-warp partials
    float* Rv  = P  + 4 * SS;             // [128]
    float* Cv  = Rv + 128;                // [128]

    const int m    = blockIdx.x;
    const int b    = m & (BSZ - 1);
    const int tid  = threadIdx.x;
    const int lane = tid & 31;
    const int wrp  = tid >> 5;
    const int g    = wrp >> 2;
    const int q    = wrp & 3;
    const int r    = 32 * g + lane;

    // ---- own x and interval index (L2-hot __ldg binary search) -------------
    const float xv_own = __ldg(x + b * NN + r);        // coalesced 128B per warp
    int lo = 0, hi = 128;
    #pragma unroll
    for (int s = 0; s < 7; ++s) {
        int mid = (lo + hi) >> 1;
        if (__ldg(g_Ts + mid) < xv_own) lo = mid + 1; else hi = mid;
    }
    const int kr_own = lo;

    // ---- warp-local prologue: 32x32 subtile, 4 rows per step ---------------
    float* mysub = sub + wrp * (32 * TS);
    const float* nz = noise + (size_t)m * (NN * NN) + (32 * g) * NN + 32 * q;
    const int oct = lane >> 3;             // 0..3 row-within-step
    const int c8  = 4 * (lane & 7);        // 0,4,..,28 column quad
    #pragma unroll
    for (int t = 0; t < 8; ++t) {
        int   src = 4 * t + oct;           // local row produced this step
        float xr  = __shfl_sync(0xffffffffu, xv_own, src);
        int   kt  = __shfl_sync(0xffffffffu, kr_own, src);
        float4 a4 = *(const float4*)(g_A  + kt * 128 + 32 * q + c8);
        float4 q4 = *(const float4*)(g_Cc + kt * 128 + 32 * q + c8);
        float4 n4 = *(const float4*)(nz + src * NN + c8);   // 128B line per octet
        float4 e;
        e.x = fex2(fmaf(n4.x, LOG2E, fmaf(a4.x, xr, q4.x)));
        e.y = fex2(fmaf(n4.y, LOG2E, fmaf(a4.y, xr, q4.y)));
        e.z = fex2(fmaf(n4.z, LOG2E, fmaf(a4.z, xr, q4.z)));
        e.w = fex2(fmaf(n4.w, LOG2E, fmaf(a4.w, xr, q4.w)));
        *(float4*)(mysub + src * TS + c8) = e;              // CF (stride 36)
    }
    __syncwarp();

    // ---- pickup own row slice (CF: banks 4*lane+4p) ------------------------
    float4 rr[8];
    #pragma unroll
    for (int p = 0; p < 8; ++p)
        rr[p] = *(const float4*)(mysub + lane * TS + 4 * p);
    const float* af = (const float*)rr;

    float R_own = 0.f;
    // ======================= iteration 0 (C == 1, peeled) ===================
    {
        float4 acc = make_float4(rr[0].x + rr[4].x, rr[0].y + rr[4].y,
                                 rr[0].z + rr[4].z, rr[0].w + rr[4].w);
        acc.x += rr[1].x + rr[5].x; acc.y += rr[1].y + rr[5].y;
        acc.z += rr[1].z + rr[5].z; acc.w += rr[1].w + rr[5].w;
        acc.x += rr[2].x + rr[6].x; acc.y += rr[2].y + rr[6].y;
        acc.z += rr[2].z + rr[6].z; acc.w += rr[2].w + rr[6].w;
        acc.x += rr[3].x + rr[7].x; acc.y += rr[3].y + rr[7].y;
        acc.z += rr[3].z + rr[7].z; acc.w += rr[3].w + rr[7].w;
        P[q * SS + r] = (acc.x + acc.y) + (acc.z + acc.w);
        __syncthreads();
        if (tid < 128) {
            float t = P[tid] + P[SS + tid] + P[2 * SS + tid] + P[3 * SS + tid];
            Rv[tid] = frcp(t);
        }
        __syncthreads();
        R_own = Rv[r];

        #pragma unroll
        for (int pass = 0; pass < 2; ++pass) {
            const int cb = 16 * pass;
            float w8[8];
            {
                bool up = (lane & 16) != 0;
                #pragma unroll
                for (int j = 0; j < 8; ++j) {
                    float a_lo = af[cb + j];
                    float a_hi = af[cb + j + 8];
                    float send = (up ? a_lo : a_hi) * R_own;
                    float keep = (up ? a_hi : a_lo);
                    float recv = __shfl_xor_sync(0xffffffffu, send, 16);
                    w8[j] = fmaf(keep, R_own, recv);
                }
            }
            #pragma unroll
            for (int off = 8; off >= 2; off >>= 1) {
                int n = off >> 1;
                bool up = (lane & off) != 0;
                #pragma unroll
                for (int j = 0; j < n; ++j) {
                    float send = up ? w8[j] : w8[j + n];
                    float keep = up ? w8[j + n] : w8[j];
                    float recv = __shfl_xor_sync(0xffffffffu, send, off);
                    w8[j] = keep + recv;
                }
            }
            float v = w8[0] + __shfl_xor_sync(0xffffffffu, w8[0], 1);
            if ((lane & 1) == 0)
                P[g * SS + 32 * q + cb + ((lane >> 1) & 15)] = v;
        }
        __syncthreads();
        if (tid < 128) {
            float t = P[tid] + P[SS + tid] + P[2 * SS + tid] + P[3 * SS + tid];
            Cv[tid] = frcp(t);
        }
        __syncthreads();
    }

    // ======================= iterations 1..9 ================================
    for (int it = 1; it < 10; ++it) {
        float4 acc = make_float4(0.f, 0.f, 0.f, 0.f);
        #pragma unroll
        for (int p = 0; p < 8; ++p) {
            float4 c4 = *(const float4*)(Cv + 32 * q + 4 * p);  // broadcast
            acc.x = fmaf(rr[p].x, c4.x, acc.x);
            acc.y = fmaf(rr[p].y, c4.y, acc.y);
            acc.z = fmaf(rr[p].z, c4.z, acc.z);
            acc.w = fmaf(rr[p].w, c4.w, acc.w);
        }
        P[q * SS + r] = (acc.x + acc.y) + (acc.z + acc.w);
        __syncthreads();
        if (tid < 128) {
            float t = P[tid] + P[SS + tid] + P[2 * SS + tid] + P[3 * SS + tid];
            Rv[tid] = frcp(t);
        }
        __syncthreads();
        R_own = Rv[r];

        #pragma unroll
        for (int pass = 0; pass < 2; ++pass) {
            const int cb = 16 * pass;
            float w8[8];
            {
                bool up = (lane & 16) != 0;
                #pragma unroll
                for (int j = 0; j < 8; ++j) {
                    float a_lo = af[cb + j];
                    float a_hi = af[cb + j + 8];
                    float send = (up ? a_lo : a_hi) * R_own;
                    float keep = (up ? a_hi : a_lo);
                    float recv = __shfl_xor_sync(0xffffffffu, send, 16);
                    w8[j] = fmaf(keep, R_own, recv);
                }
            }
            #pragma unroll
            for (int off = 8; off >= 2; off >>= 1) {
                int n = off >> 1;
                bool up = (lane & off) != 0;
                #pragma unroll
                for (int j = 0; j < n; ++j) {
                    float send = up ? w8[j] : w8[j + n];
                    float keep = up ? w8[j + n] : w8[j];
                    float recv = __shfl_xor_sync(0xffffffffu, send, off);
                    w8[j] = keep + recv;
                }
            }
            float v = w8[0] + __shfl_xor_sync(0xffffffffu, w8[0], 1);
            if ((lane & 1) == 0)
                P[g * SS + 32 * q + cb + ((lane >> 1) & 15)] = v;
        }
        __syncthreads();
        if (tid < 128) {
            float t = P[tid] + P[SS + tid] + P[2 * SS + tid] + P[3 * SS + tid];
            Cv[tid] = frcp(t);
        }
        __syncthreads();
    }

    // ---- epilogue: out[m][c][r] = M0[r][c]*R_r*C_c, DIRECT from registers --
    {
        float* om = out + (size_t)m * (NN * NN) + (32 * q) * NN + 32 * g + lane;
        #pragma unroll
        for (int p = 0; p < 8; ++p) {
            float4 c4 = *(const float4*)(Cv + 32 * q + 4 * p);  // broadcast
            float sx = rr[p].x * R_own, sy = rr[p].y * R_own;
            float sz = rr[p].z * R_own, sw = rr[p].w * R_own;
            om[(4 * p + 0) * NN] = sx * c4.x;   // coalesced 128B STG.32
            om[(4 * p + 1) * NN] = sy * c4.y;
            om[(4 * p + 2) * NN] = sz * c4.z;
            om[(4 * p + 3) * NN] = sw * c4.w;
        }
    }
}

// ---------------- launch ----------------------------------------------------
extern "C" void kernel_launch(void* const* d_in, const int* in_sizes, int n_in,
                              void* d_out, int out_size)
{
    const float* x     = (const float*)d_in[0];
    const float* w1    = (const float*)d_in[1];
    const float* b1    = (const float*)d_in[2];
    const float* w2    = (const float*)d_in[3];
    const float* b2    = (const float*)d_in[4];
    const float* noise = (const float*)d_in[5];
    float* out = (float*)d_out;

    const int prep_smem = 128 * 129 * 4;                    // 66,048 B
    cudaFuncSetAttribute(k_prep, cudaFuncAttributeMaxDynamicSharedMemorySize,
                         prep_smem);
    k_prep<<<129, 128, prep_smem>>>(w1, b1, w2, b2);

    // sub + P + Rv + Cv
    const int smem_words = 16 * 32 * TS + 4 * SS + 2 * 128;
    const int smem_bytes = smem_words * 4;                  // 76,864 B
    cudaFuncSetAttribute(k_sinkhorn, cudaFuncAttributeMaxDynamicSharedMemorySize,
                         smem_bytes);
    k_sinkhorn<<<NMAT, 512, smem_bytes>>>(x, noise, out);
}